// round 15
// baseline (speedup 1.0000x reference)
#include <cuda_runtime.h>
#include <math.h>

// Problem dims
#define S  64
#define H  1024
#define V  512
#define WV 300
#define NE 512

// Recurrent kernel config: ONE cluster of 16 CTAs x 512 threads.
// Thread patch: g = tid&7 -> cols [blk*64 + g*8, +8), s = tid>>3 -> rows [s*8, +8)
#define RB  16
#define RC  64
#define RT  512

// Output offsets (reference return order)
#define OFF_ENTP 0
#define OFF_ACP  (S*NE)
#define OFF_ENT  (OFF_ACP + S*V)
#define OFF_ALL  (OFF_ENT + S*H)
#define OFF_ACT  (OFF_ALL + (size_t)S*NE*H)

// Scratch (device globals; no allocation allowed)
__device__ __align__(16) float g_HH[64*2048];     // dense [relu(h) | relu(hat)]
__device__ __align__(16) float g_ACd[64*512];     // dense sigmoid(ac)
__device__ __align__(16) float g_GP3[8*64*1024];  // w2v split-K partials
__device__ __align__(16) float g_W2V[S*H];
__device__ float g_CHOICE[S*2];
__device__ float g_SCAL[S];
// u partials, p-major, double buffered: [buf][p][entity], p = CTA 0..15
__device__ __align__(16) float g_PART[2][RB*NE];

// ---------------------------------------------------------------------------
// Dense split-N GEMM: Out[64,N] = act( X[64,K] @ W[N,K]^T + b )
// ---------------------------------------------------------------------------
__global__ void __launch_bounds__(256) gemm32(
    const float* __restrict__ X, int xstride,
    const float* __restrict__ Wa, const float* __restrict__ Wb, int NB,
    const float* __restrict__ bA, const float* __restrict__ bB,
    float* __restrict__ Out, int ostride, int K, int act)
{
    __shared__ __align__(8) float Xs[32][34];
    __shared__ __align__(8) float Ws[32][34];
    int tid = threadIdx.x;
    int tx = tid & 15, ty = tid >> 4;
    int n0 = blockIdx.x * 32;
    int m0 = blockIdx.y * 32;

    float a00 = 0.f, a01 = 0.f, a10 = 0.f, a11 = 0.f;

    for (int kc = 0; kc < K; kc += 32) {
#pragma unroll
        for (int i = 0; i < 4; i++) {
            int e = tid + 256*i; int row = e >> 5, kk = e & 31;
            Xs[kk][row] = X[(size_t)(m0 + row)*xstride + kc + kk];
        }
#pragma unroll
        for (int i = 0; i < 4; i++) {
            int e = tid + 256*i; int nr = e >> 5, kk = e & 31;
            int n = n0 + nr;
            const float* Wp = (n < NB) ? (Wa + (size_t)n*K) : (Wb + (size_t)(n - NB)*K);
            Ws[kk][nr] = Wp[kc + kk];
        }
        __syncthreads();
#pragma unroll
        for (int kk = 0; kk < 32; kk++) {
            float x0 = Xs[kk][ty*2], x1 = Xs[kk][ty*2+1];
            float w0 = Ws[kk][tx*2], w1 = Ws[kk][tx*2+1];
            a00 += x0*w0; a01 += x0*w1;
            a10 += x1*w0; a11 += x1*w1;
        }
        __syncthreads();
    }

    int n = n0 + tx*2;
    float b0 = (n   < NB) ? bA[n]   : bB[n   - NB];
    float b1 = (n+1 < NB) ? bA[n+1] : bB[n+1 - NB];
    float r[2][2] = {{a00 + b0, a01 + b1}, {a10 + b0, a11 + b1}};
#pragma unroll
    for (int q = 0; q < 2; q++)
#pragma unroll
        for (int p = 0; p < 2; p++) {
            float v = r[q][p];
            if (act == 1)      v = fmaxf(v, 0.f);
            else if (act == 2) v = 1.f/(1.f + expf(-v));
            Out[(size_t)(m0 + ty*2 + q)*ostride + n0 + tx*2 + p] = v;
        }
}

// ---------------------------------------------------------------------------
// Split-K GEMM for w2v partials: GP3[ky][64][1024] = [relu(hat)|sig(ac)] @ W2w^T
// ---------------------------------------------------------------------------
__global__ void __launch_bounds__(256) gemm3(
    const float* __restrict__ W, float* __restrict__ OutP, int N, int K, int kslice)
{
    __shared__ __align__(16) float XsT[32][68];
    __shared__ __align__(16) float WsT[32][68];
    int tid = threadIdx.x;
    int tx = tid & 15, ty = tid >> 4;
    int n0 = blockIdx.x * 64;
    int kc0 = blockIdx.y * kslice;

    float acc[4][4];
#pragma unroll
    for (int r = 0; r < 4; r++)
#pragma unroll
        for (int q = 0; q < 4; q++) acc[r][q] = 0.f;

    for (int kc = kc0; kc < kc0 + kslice; kc += 32) {
#pragma unroll
        for (int i = 0; i < 8; i++) {
            int e = tid + 256*i; int row = e >> 5, kk = e & 31;
            int k = kc + kk;
            XsT[kk][row] = (k < 1024) ? g_HH[row*2048 + 1024 + k]
                                      : g_ACd[row*512 + (k - 1024)];
        }
#pragma unroll
        for (int i = 0; i < 8; i++) {
            int e = tid + 256*i; int nr = e >> 5, kk = e & 31;
            WsT[kk][nr] = W[(size_t)(n0 + nr)*K + kc + kk];
        }
        __syncthreads();
#pragma unroll
        for (int kk = 0; kk < 32; kk++) {
            float4 xa = *(const float4*)&XsT[kk][ty*4];
            float4 wb = *(const float4*)&WsT[kk][tx*4];
            acc[0][0] += xa.x*wb.x; acc[0][1] += xa.x*wb.y; acc[0][2] += xa.x*wb.z; acc[0][3] += xa.x*wb.w;
            acc[1][0] += xa.y*wb.x; acc[1][1] += xa.y*wb.y; acc[1][2] += xa.y*wb.z; acc[1][3] += xa.y*wb.w;
            acc[2][0] += xa.z*wb.x; acc[2][1] += xa.z*wb.y; acc[2][2] += xa.z*wb.z; acc[2][3] += xa.z*wb.w;
            acc[3][0] += xa.w*wb.x; acc[3][1] += xa.w*wb.y; acc[3][2] += xa.w*wb.z; acc[3][3] += xa.w*wb.w;
        }
        __syncthreads();
    }
    float* Po = OutP + (size_t)blockIdx.y*64*N + n0;
#pragma unroll
    for (int r = 0; r < 4; r++) {
        float4 v = make_float4(acc[r][0], acc[r][1], acc[r][2], acc[r][3]);
        *(float4*)&Po[(size_t)(ty*4 + r)*N + tx*4] = v;
    }
}

#define CLUSTER_ARRIVE() asm volatile("barrier.cluster.arrive.aligned;" ::: "memory")
#define CLUSTER_WAIT()   asm volatile("barrier.cluster.wait.aligned;" ::: "memory")

// ---------------------------------------------------------------------------
// Persistent recurrent kernel: one 16-CTA cluster, hardware cluster barrier.
// ---------------------------------------------------------------------------
__global__ void __launch_bounds__(RT, 1) k_recurrent(
    const float* __restrict__ evin,
    const float* __restrict__ emb,
    const float* __restrict__ W2b,
    const float* __restrict__ W3w, const float* __restrict__ W3b,
    const float* __restrict__ W4w, const float* __restrict__ W4b,
    float* __restrict__ out)
{
    int tid = threadIdx.x;
    int blk = blockIdx.x;
    int g = tid & 7;          // col group (8 cols)
    int s = tid >> 3;         // row segment (8 rows), 0..63
    int jc = blk*RC + g*8;    // first col of this thread's group
    int i0 = s*8;             // first row (entity)
    int lane = tid & 31, wid = tid >> 5;

    __shared__ __align__(16) float s_attn[NE];
    // row stride 68 floats = 272 B = 17*16 B -> float4 stores at lane*8(+4) aligned
    __shared__ __align__(16) float s_pc[16][68];
    __shared__ __align__(16) float s_kt[RC];
    __shared__ float s_red[16];
    __shared__ float s_sum;
    __shared__ float s_c0[S], s_c1[S], s_scal[S];
    __shared__ float s_ac[V];
    __shared__ float s_bf[WV];
    __shared__ float s_cl[3];

    // ev patch in registers (8 rows x 8 cols = 16 float4); issue early
    float4 evr[16];
#pragma unroll
    for (int r = 0; r < 8; r++) {
        evr[2*r+0] = *(const float4*)(evin + (size_t)(i0 + r)*H + jc);
        evr[2*r+1] = *(const float4*)(evin + (size_t)(i0 + r)*H + jc + 4);
    }

    // ============ prologue: smalls for steps t = blk, +16, +32, +48 ========
    for (int t = blk; t < S; t += RB) {
        float a = g_ACd[t*V + tid];
        s_ac[tid] = a;
        out[OFF_ACP + t*V + tid] = a;
        float v = a;
#pragma unroll
        for (int o = 16; o; o >>= 1) v += __shfl_xor_sync(0xffffffffu, v, o);
        if (lane == 0) s_red[wid] = v;
        __syncthreads();
        if (tid < 16) {
            float x = s_red[tid];
#pragma unroll
            for (int o = 8; o; o >>= 1) x += __shfl_xor_sync(0x0000ffffu, x, o);
            if (tid == 0) s_sum = x;
        }
        __syncthreads();
        float acsum = s_sum;

        if (tid < WV) {
            float a0 = 0.f, a1 = 0.f, a2 = 0.f, a3 = 0.f;
            for (int i = 0; i < V; i += 4) {
                a0 += s_ac[i+0]*emb[(i+0)*WV + tid];
                a1 += s_ac[i+1]*emb[(i+1)*WV + tid];
                a2 += s_ac[i+2]*emb[(i+2)*WV + tid];
                a3 += s_ac[i+3]*emb[(i+3)*WV + tid];
            }
            float bf = __fdividef((a0+a1)+(a2+a3), acsum);
            s_bf[tid] = bf;
            out[OFF_ACT + t*WV + tid] = bf;
        }
        __syncthreads();

        float p = (tid < WV) ? s_bf[tid]*W4w[tid] : 0.f;
#pragma unroll
        for (int o = 16; o; o >>= 1) p += __shfl_xor_sync(0xffffffffu, p, o);
        if (lane == 0) s_red[wid] = p;
        __syncthreads();
        if (tid < 16) {
            float x = s_red[tid];
#pragma unroll
            for (int o = 8; o; o >>= 1) x += __shfl_xor_sync(0x0000ffffu, x, o);
            if (tid == 0) g_SCAL[t] = x + W4b[0];
        }

        if (wid < 3) {
            float a3v = 0.f;
            for (int k = lane; k < H; k += 32)
                a3v += g_HH[t*2048 + 1024 + k]*W3w[wid*H + k];
#pragma unroll
            for (int o = 16; o; o >>= 1) a3v += __shfl_xor_sync(0xffffffffu, a3v, o);
            if (lane == 0) s_cl[wid] = a3v + W3b[wid];
        }
        __syncthreads();
        if (tid == 0) {
            float m = fmaxf(s_cl[0], fmaxf(s_cl[1], s_cl[2]));
            float e0 = __expf(s_cl[0]-m), e1 = __expf(s_cl[1]-m), e2 = __expf(s_cl[2]-m);
            float sm = e0 + e1 + e2;
            g_CHOICE[t*2+0] = __fdividef(e0, sm);
            g_CHOICE[t*2+1] = __fdividef(e1, sm);
        }

        // w2v[t] = W2b + sum_ky GP3[ky][t][:]
#pragma unroll
        for (int h2 = 0; h2 < 2; h2++) {
            int n = tid + 512*h2;
            float w = W2b[n];
#pragma unroll
            for (int ky = 0; ky < 8; ky++) w += g_GP3[ky*64*1024 + t*1024 + n];
            g_W2V[t*H + n] = w;
        }
        __syncthreads();
    }
    CLUSTER_ARRIVE(); CLUSTER_WAIT();

    // cache step constants in smem (visible after cluster sync)
    if (tid < S) {
        s_c0[tid]   = __ldcg(&g_CHOICE[tid*2+0]);
        s_c1[tid]   = __ldcg(&g_CHOICE[tid*2+1]);
        s_scal[tid] = __ldcg(&g_SCAL[tid]);
    }

    // logit0 partials -> p-major g_PART[0][blk][*]
    {
        float4 wa = __ldcg((const float4*)(g_W2V + jc));
        float4 wb = __ldcg((const float4*)(g_W2V + jc + 4));
        float lp[8];
#pragma unroll
        for (int r = 0; r < 8; r++) {
            float4 ea = evr[2*r], eb = evr[2*r+1];
            lp[r] = (ea.x*wa.x + ea.y*wa.y + ea.z*wa.z + ea.w*wa.w)
                  + (eb.x*wb.x + eb.y*wb.y + eb.z*wb.z + eb.w*wb.w);
        }
#pragma unroll
        for (int r = 0; r < 8; r++) {
            lp[r] += __shfl_xor_sync(0xffffffffu, lp[r], 1);
            lp[r] += __shfl_xor_sync(0xffffffffu, lp[r], 2);
            lp[r] += __shfl_xor_sync(0xffffffffu, lp[r], 4);
        }
        if (g == 0) {
            float* po = g_PART[0] + blk*NE + i0;
            *(float4*)(po)     = make_float4(lp[0], lp[1], lp[2], lp[3]);
            *(float4*)(po + 4) = make_float4(lp[4], lp[5], lp[6], lp[7]);
        }
    }
    CLUSTER_ARRIVE(); CLUSTER_WAIT();

    // ========================= 64 sequential steps =========================
    float prevE = 0.f;
    for (int t = 0; t < S; t++) {
        float c0   = s_c0[t];
        float c1   = s_c1[t];
        float scal = s_scal[t];

        // gather entity tid's 16 partials (p-major, coalesced)
        const float* pp = g_PART[t & 1] + tid;
        float q0 = 0.f, q1 = 0.f, q2 = 0.f, q3 = 0.f;
#pragma unroll
        for (int bb = 0; bb < RB; bb += 4) {
            q0 += __ldcg(pp + (bb+0)*NE);
            q1 += __ldcg(pp + (bb+1)*NE);
            q2 += __ldcg(pp + (bb+2)*NE);
            q3 += __ldcg(pp + (bb+3)*NE);
        }
        float lg = (q0 + q1) + (q2 + q3);
        float ent = __fdividef(1.f, 1.f + __expf(-lg));
        float at = fmaf(c0, ent, c1*prevE);
        prevE = ent;
        s_attn[tid] = at;
        __syncthreads();

        // asum: redundant per-warp sum of s_attn (conflict-free LDS.128)
        float asum;
        {
            float4 t0 = *(const float4*)&s_attn[lane*4];
            float4 t1 = *(const float4*)&s_attn[lane*4 + 128];
            float4 t2 = *(const float4*)&s_attn[lane*4 + 256];
            float4 t3 = *(const float4*)&s_attn[lane*4 + 384];
            float v = ((t0.x+t0.y)+(t0.z+t0.w)) + ((t1.x+t1.y)+(t1.z+t1.w))
                    + ((t2.x+t2.y)+(t2.z+t2.w)) + ((t3.x+t3.y)+(t3.z+t3.w));
#pragma unroll
            for (int o = 16; o; o >>= 1) v += __shfl_xor_sync(0xffffffffu, v, o);
            asum = v;
        }

        // bar_et partial over 8 rows x 8 cols; reduce the warp's 4 segments
        float4 ba = make_float4(0.f,0.f,0.f,0.f), bb4 = make_float4(0.f,0.f,0.f,0.f);
#pragma unroll
        for (int r = 0; r < 8; r++) {
            float a = s_attn[i0 + r];
            float4 ea = evr[2*r], eb = evr[2*r+1];
            ba.x = fmaf(a, ea.x, ba.x); ba.y = fmaf(a, ea.y, ba.y);
            ba.z = fmaf(a, ea.z, ba.z); ba.w = fmaf(a, ea.w, ba.w);
            bb4.x = fmaf(a, eb.x, bb4.x); bb4.y = fmaf(a, eb.y, bb4.y);
            bb4.z = fmaf(a, eb.z, bb4.z); bb4.w = fmaf(a, eb.w, bb4.w);
        }
#pragma unroll
        for (int o = 8; o <= 16; o <<= 1) {
            ba.x += __shfl_xor_sync(0xffffffffu, ba.x, o);
            ba.y += __shfl_xor_sync(0xffffffffu, ba.y, o);
            ba.z += __shfl_xor_sync(0xffffffffu, ba.z, o);
            ba.w += __shfl_xor_sync(0xffffffffu, ba.w, o);
            bb4.x += __shfl_xor_sync(0xffffffffu, bb4.x, o);
            bb4.y += __shfl_xor_sync(0xffffffffu, bb4.y, o);
            bb4.z += __shfl_xor_sync(0xffffffffu, bb4.z, o);
            bb4.w += __shfl_xor_sync(0xffffffffu, bb4.w, o);
        }
        if (lane < 8) {
            *(float4*)&s_pc[wid][lane*8]     = ba;
            *(float4*)&s_pc[wid][lane*8 + 4] = bb4;
        }
        __syncthreads();
        if (tid < RC) {
            float bs = 0.f;
#pragma unroll
            for (int w = 0; w < 16; w++) bs += s_pc[w][tid];
            float bar = __fdividef(bs, asum);
            out[OFF_ENT + t*H + blk*RC + tid] = bar;
            s_kt[tid] = fmaxf(scal*bar, 0.f);
        }
        __syncthreads();
        float4 kta = *(const float4*)&s_kt[g*8];
        float4 ktb = *(const float4*)&s_kt[g*8 + 4];

        if (t < S-1) {
            float4 wa = __ldcg((const float4*)(g_W2V + (t+1)*H + jc));
            float4 wb = __ldcg((const float4*)(g_W2V + (t+1)*H + jc + 4));
            float lp[8];
#pragma unroll
            for (int r = 0; r < 8; r++) {
                float a = s_attn[i0 + r];
                float4 ea = evr[2*r], eb = evr[2*r+1];
                ea.x = fmaf(a, kta.x - ea.x, ea.x); ea.y = fmaf(a, kta.y - ea.y, ea.y);
                ea.z = fmaf(a, kta.z - ea.z, ea.z); ea.w = fmaf(a, kta.w - ea.w, ea.w);
                eb.x = fmaf(a, ktb.x - eb.x, eb.x); eb.y = fmaf(a, ktb.y - eb.y, eb.y);
                eb.z = fmaf(a, ktb.z - eb.z, eb.z); eb.w = fmaf(a, ktb.w - eb.w, eb.w);
                evr[2*r] = ea; evr[2*r+1] = eb;
                lp[r] = (ea.x*wa.x + ea.y*wa.y + ea.z*wa.z + ea.w*wa.w)
                      + (eb.x*wb.x + eb.y*wb.y + eb.z*wb.z + eb.w*wb.w);
            }
#pragma unroll
            for (int r = 0; r < 8; r++) {
                lp[r] += __shfl_xor_sync(0xffffffffu, lp[r], 1);
                lp[r] += __shfl_xor_sync(0xffffffffu, lp[r], 2);
                lp[r] += __shfl_xor_sync(0xffffffffu, lp[r], 4);
            }
            if (g == 0) {
                float* po = g_PART[(t+1) & 1] + blk*NE + i0;
                *(float4*)(po)     = make_float4(lp[0], lp[1], lp[2], lp[3]);
                *(float4*)(po + 4) = make_float4(lp[4], lp[5], lp[6], lp[7]);
            }

            // HW cluster barrier: arrive (releases partial stores), bulk
            // output stores drain between arrive and wait.
            CLUSTER_ARRIVE();
            if (wid == blk) out[OFF_ENTP + t*NE + tid] = ent;
            {
                float* snap = out + OFF_ALL + (size_t)t*NE*H + jc;
#pragma unroll
                for (int r = 0; r < 8; r++) {
                    __stcs((float4*)(snap + (size_t)(i0 + r)*H),     evr[2*r]);
                    __stcs((float4*)(snap + (size_t)(i0 + r)*H + 4), evr[2*r+1]);
                }
            }
            CLUSTER_WAIT();
        } else {
#pragma unroll
            for (int r = 0; r < 8; r++) {
                float a = s_attn[i0 + r];
                float4 ea = evr[2*r], eb = evr[2*r+1];
                ea.x = fmaf(a, kta.x - ea.x, ea.x); ea.y = fmaf(a, kta.y - ea.y, ea.y);
                ea.z = fmaf(a, kta.z - ea.z, ea.z); ea.w = fmaf(a, kta.w - ea.w, ea.w);
                eb.x = fmaf(a, ktb.x - eb.x, eb.x); eb.y = fmaf(a, ktb.y - eb.y, eb.y);
                eb.z = fmaf(a, ktb.z - eb.z, eb.z); eb.w = fmaf(a, ktb.w - eb.w, eb.w);
                evr[2*r] = ea; evr[2*r+1] = eb;
            }
            if (wid == blk) out[OFF_ENTP + t*NE + tid] = ent;
            float* snap = out + OFF_ALL + (size_t)t*NE*H + jc;
#pragma unroll
            for (int r = 0; r < 8; r++) {
                __stcs((float4*)(snap + (size_t)(i0 + r)*H),     evr[2*r]);
                __stcs((float4*)(snap + (size_t)(i0 + r)*H + 4), evr[2*r+1]);
            }
        }
    }
}

// ---------------------------------------------------------------------------
extern "C" void kernel_launch(void* const* d_in, const int* in_sizes, int n_in,
                              void* d_out, int out_size)
{
    (void)in_sizes; (void)n_in; (void)out_size;
    const float* vv  = (const float*)d_in[0];
    const float* ev  = (const float*)d_in[1];
    const float* A1w = (const float*)d_in[2];
    const float* A1b = (const float*)d_in[3];
    const float* A2w = (const float*)d_in[4];
    const float* A2b = (const float*)d_in[5];
    const float* emb = (const float*)d_in[6];
    const float* W1w = (const float*)d_in[7];
    const float* W1b = (const float*)d_in[8];
    const float* W2w = (const float*)d_in[9];
    const float* W2b = (const float*)d_in[10];
    const float* W3w = (const float*)d_in[11];
    const float* W3b = (const float*)d_in[12];
    const float* W4w = (const float*)d_in[13];
    const float* W4b = (const float*)d_in[14];
    float* out = (float*)d_out;

    float *pHH, *pAC, *pGP3;
    cudaGetSymbolAddress((void**)&pHH,  g_HH);
    cudaGetSymbolAddress((void**)&pAC,  g_ACd);
    cudaGetSymbolAddress((void**)&pGP3, g_GP3);

    // 0: [h|hat] = relu(vv @ [A1w|W1w]^T + bias)
    gemm32<<<dim3(64, 2), 256>>>(vv, H, A1w, W1w, 1024, A1b, W1b, pHH, 2048, H, 1);
    // 1: ac = sigmoid(h @ A2w^T + A2b)
    gemm32<<<dim3(16, 2), 256>>>(pHH, 2048, A2w, A2w, 1<<30, A2b, A2b, pAC, 512, H, 2);
    // 2: w2v partials
    gemm3<<<dim3(16, 8), 256>>>(W2w, pGP3, 1024, 1536, 192);

    // 3: recurrence as ONE 16-CTA cluster (hardware cluster barrier)
    cudaFuncSetAttribute(k_recurrent,
                         cudaFuncAttributeNonPortableClusterSizeAllowed, 1);
    cudaLaunchConfig_t cfg = {};
    cfg.gridDim  = dim3(RB, 1, 1);
    cfg.blockDim = dim3(RT, 1, 1);
    cudaLaunchAttribute attrs[1];
    attrs[0].id = cudaLaunchAttributeClusterDimension;
    attrs[0].val.clusterDim.x = RB;
    attrs[0].val.clusterDim.y = 1;
    attrs[0].val.clusterDim.z = 1;
    cfg.attrs = attrs;
    cfg.numAttrs = 1;
    cudaLaunchKernelEx(&cfg, k_recurrent,
                       ev, emb, W2b, W3w, W3b, W4w, W4b, out);
}

// round 16
// speedup vs baseline: 1.7025x; 1.7025x over previous
#include <cuda_runtime.h>
#include <math.h>

// Problem dims
#define S  64
#define H  1024
#define V  512
#define WV 300
#define NE 512

// Recurrent kernel config: 32 blocks x 512 threads.
// Thread patch: g = tid&7 -> cols [blk*32 + g*4, +4), s = tid>>3 -> rows [s*8, +8)
#define RB  32
#define RC  32
#define RT  512

// Output offsets (reference return order)
#define OFF_ENTP 0
#define OFF_ACP  (S*NE)
#define OFF_ENT  (OFF_ACP + S*V)
#define OFF_ALL  (OFF_ENT + S*H)
#define OFF_ACT  (OFF_ALL + (size_t)S*NE*H)

// Scratch (device globals; no allocation allowed)
__device__ __align__(16) float g_HH[64*2048];     // dense [relu(h) | relu(hat)]
__device__ __align__(16) float g_ACd[64*512];     // dense sigmoid(ac)
__device__ __align__(16) float g_GP3[8*64*1024];  // w2v split-K partials
__device__ __align__(16) float g_W2V[S*H];
__device__ float g_CHOICE[S*2];
__device__ float g_SCAL[S];
// u partials, p-major, double buffered: [buf][p][entity]
__device__ __align__(16) float g_PART[2][RB*NE];
__device__ __align__(128) unsigned g_cnt;          // central barrier counter
__device__ unsigned g_pad0[31];                    // keep g_cnt line private

// ---------------------------------------------------------------------------
// Dense split-N GEMM: Out[64,N] = act( X[64,K] @ W[N,K]^T + b )
// Block (0,0) also resets the barrier counter (runs before k_recurrent).
// ---------------------------------------------------------------------------
__global__ void __launch_bounds__(256) gemm32(
    const float* __restrict__ X, int xstride,
    const float* __restrict__ Wa, const float* __restrict__ Wb, int NB,
    const float* __restrict__ bA, const float* __restrict__ bB,
    float* __restrict__ Out, int ostride, int K, int act)
{
    if (blockIdx.x == 0 && blockIdx.y == 0 && threadIdx.x == 0) {
        g_cnt = 0u;
    }
    __shared__ __align__(8) float Xs[32][34];
    __shared__ __align__(8) float Ws[32][34];
    int tid = threadIdx.x;
    int tx = tid & 15, ty = tid >> 4;
    int n0 = blockIdx.x * 32;
    int m0 = blockIdx.y * 32;

    float a00 = 0.f, a01 = 0.f, a10 = 0.f, a11 = 0.f;

    for (int kc = 0; kc < K; kc += 32) {
#pragma unroll
        for (int i = 0; i < 4; i++) {
            int e = tid + 256*i; int row = e >> 5, kk = e & 31;
            Xs[kk][row] = X[(size_t)(m0 + row)*xstride + kc + kk];
        }
#pragma unroll
        for (int i = 0; i < 4; i++) {
            int e = tid + 256*i; int nr = e >> 5, kk = e & 31;
            int n = n0 + nr;
            const float* Wp = (n < NB) ? (Wa + (size_t)n*K) : (Wb + (size_t)(n - NB)*K);
            Ws[kk][nr] = Wp[kc + kk];
        }
        __syncthreads();
#pragma unroll
        for (int kk = 0; kk < 32; kk++) {
            float x0 = Xs[kk][ty*2], x1 = Xs[kk][ty*2+1];
            float w0 = Ws[kk][tx*2], w1 = Ws[kk][tx*2+1];
            a00 += x0*w0; a01 += x0*w1;
            a10 += x1*w0; a11 += x1*w1;
        }
        __syncthreads();
    }

    int n = n0 + tx*2;
    float b0 = (n   < NB) ? bA[n]   : bB[n   - NB];
    float b1 = (n+1 < NB) ? bA[n+1] : bB[n+1 - NB];
    float r[2][2] = {{a00 + b0, a01 + b1}, {a10 + b0, a11 + b1}};
#pragma unroll
    for (int q = 0; q < 2; q++)
#pragma unroll
        for (int p = 0; p < 2; p++) {
            float v = r[q][p];
            if (act == 1)      v = fmaxf(v, 0.f);
            else if (act == 2) v = 1.f/(1.f + expf(-v));
            Out[(size_t)(m0 + ty*2 + q)*ostride + n0 + tx*2 + p] = v;
        }
}

// ---------------------------------------------------------------------------
// Split-K GEMM for w2v partials: GP3[ky][64][1024] = [relu(hat)|sig(ac)] @ W2w^T
// ---------------------------------------------------------------------------
__global__ void __launch_bounds__(256) gemm3(
    const float* __restrict__ W, float* __restrict__ OutP, int N, int K, int kslice)
{
    __shared__ __align__(16) float XsT[32][68];
    __shared__ __align__(16) float WsT[32][68];
    int tid = threadIdx.x;
    int tx = tid & 15, ty = tid >> 4;
    int n0 = blockIdx.x * 64;
    int kc0 = blockIdx.y * kslice;

    float acc[4][4];
#pragma unroll
    for (int r = 0; r < 4; r++)
#pragma unroll
        for (int q = 0; q < 4; q++) acc[r][q] = 0.f;

    for (int kc = kc0; kc < kc0 + kslice; kc += 32) {
#pragma unroll
        for (int i = 0; i < 8; i++) {
            int e = tid + 256*i; int row = e >> 5, kk = e & 31;
            int k = kc + kk;
            XsT[kk][row] = (k < 1024) ? g_HH[row*2048 + 1024 + k]
                                      : g_ACd[row*512 + (k - 1024)];
        }
#pragma unroll
        for (int i = 0; i < 8; i++) {
            int e = tid + 256*i; int nr = e >> 5, kk = e & 31;
            WsT[kk][nr] = W[(size_t)(n0 + nr)*K + kc + kk];
        }
        __syncthreads();
#pragma unroll
        for (int kk = 0; kk < 32; kk++) {
            float4 xa = *(const float4*)&XsT[kk][ty*4];
            float4 wb = *(const float4*)&WsT[kk][tx*4];
            acc[0][0] += xa.x*wb.x; acc[0][1] += xa.x*wb.y; acc[0][2] += xa.x*wb.z; acc[0][3] += xa.x*wb.w;
            acc[1][0] += xa.y*wb.x; acc[1][1] += xa.y*wb.y; acc[1][2] += xa.y*wb.z; acc[1][3] += xa.y*wb.w;
            acc[2][0] += xa.z*wb.x; acc[2][1] += xa.z*wb.y; acc[2][2] += xa.z*wb.z; acc[2][3] += xa.z*wb.w;
            acc[3][0] += xa.w*wb.x; acc[3][1] += xa.w*wb.y; acc[3][2] += xa.w*wb.z; acc[3][3] += xa.w*wb.w;
        }
        __syncthreads();
    }
    float* Po = OutP + (size_t)blockIdx.y*64*N + n0;
#pragma unroll
    for (int r = 0; r < 4; r++) {
        float4 v = make_float4(acc[r][0], acc[r][1], acc[r][2], acc[r][3]);
        *(float4*)&Po[(size_t)(ty*4 + r)*N + tx*4] = v;
    }
}

// ---------------------------------------------------------------------------
// Persistent recurrent kernel (launch index 3; profiled). R11 structure.
// ---------------------------------------------------------------------------
__global__ void __launch_bounds__(RT, 1) k_recurrent(
    const float* __restrict__ evin,
    const float* __restrict__ emb,
    const float* __restrict__ W2b,
    const float* __restrict__ W3w, const float* __restrict__ W3b,
    const float* __restrict__ W4w, const float* __restrict__ W4b,
    float* __restrict__ out)
{
    int tid = threadIdx.x;
    int blk = blockIdx.x;
    int g = tid & 7;          // col group (4 cols), 8 groups
    int s = tid >> 3;         // row segment (8 rows), 0..63
    int jc = blk*RC + g*4;    // first col of this thread's group
    int i0 = s*8;             // first row
    int lane = tid & 31, wid = tid >> 5;

    __shared__ __align__(16) float s_attn[NE];
    __shared__ __align__(16) float s_pc[16][8][4];   // [warp][g][col-in-group]
    __shared__ __align__(16) float s_kt[RC];
    __shared__ float s_red[16];
    __shared__ float s_sum;
    __shared__ unsigned s_old;
    __shared__ float s_c0[S], s_c1[S], s_scal[S];
    __shared__ float s_ac[V];
    __shared__ float s_bf[WV];
    __shared__ float s_cl[3];

    // ev patch in registers (issue early; overlaps prologue)
    float4 evr[8];
#pragma unroll
    for (int r = 0; r < 8; r++)
        evr[r] = *(const float4*)(evin + (size_t)(i0 + r)*H + jc);

#define BAR_ARRIVE() do { \
        __syncthreads(); \
        if (tid == 0) { \
            unsigned _old; \
            asm volatile("atom.acq_rel.gpu.global.add.u32 %0, [%1], 1;" \
                         : "=r"(_old) : "l"(&g_cnt) : "memory"); \
            s_old = _old; \
        } \
    } while (0)
#define BAR_WAIT(genv) do { \
        unsigned _tgt = 32u*(unsigned)(genv); \
        if (tid < 32) { \
            __syncwarp(); \
            if (s_old != _tgt - 1u) { \
                unsigned _c; \
                do { asm volatile("ld.acquire.gpu.global.u32 %0, [%1];" \
                                  : "=r"(_c) : "l"(&g_cnt) : "memory"); \
                } while (_c < _tgt); \
            } \
        } \
        __syncthreads(); \
    } while (0)

    // ============ prologue: smalls for steps t = blk and blk+32 ============
    for (int t = blk; t < S; t += RB) {
        float a = g_ACd[t*V + tid];
        s_ac[tid] = a;
        out[OFF_ACP + t*V + tid] = a;
        float v = a;
#pragma unroll
        for (int o = 16; o; o >>= 1) v += __shfl_xor_sync(0xffffffffu, v, o);
        if (lane == 0) s_red[wid] = v;
        __syncthreads();
        if (tid < 16) {
            float x = s_red[tid];
#pragma unroll
            for (int o = 8; o; o >>= 1) x += __shfl_xor_sync(0x0000ffffu, x, o);
            if (tid == 0) s_sum = x;
        }
        __syncthreads();
        float acsum = s_sum;

        if (tid < WV) {
            float a0 = 0.f, a1 = 0.f, a2 = 0.f, a3 = 0.f;
            for (int i = 0; i < V; i += 4) {
                a0 += s_ac[i+0]*emb[(i+0)*WV + tid];
                a1 += s_ac[i+1]*emb[(i+1)*WV + tid];
                a2 += s_ac[i+2]*emb[(i+2)*WV + tid];
                a3 += s_ac[i+3]*emb[(i+3)*WV + tid];
            }
            float bf = __fdividef((a0+a1)+(a2+a3), acsum);
            s_bf[tid] = bf;
            out[OFF_ACT + t*WV + tid] = bf;
        }
        __syncthreads();

        float p = (tid < WV) ? s_bf[tid]*W4w[tid] : 0.f;
#pragma unroll
        for (int o = 16; o; o >>= 1) p += __shfl_xor_sync(0xffffffffu, p, o);
        if (lane == 0) s_red[wid] = p;
        __syncthreads();
        if (tid < 16) {
            float x = s_red[tid];
#pragma unroll
            for (int o = 8; o; o >>= 1) x += __shfl_xor_sync(0x0000ffffu, x, o);
            if (tid == 0) g_SCAL[t] = x + W4b[0];
        }

        if (wid < 3) {
            float a3v = 0.f;
            for (int k = lane; k < H; k += 32)
                a3v += g_HH[t*2048 + 1024 + k]*W3w[wid*H + k];
#pragma unroll
            for (int o = 16; o; o >>= 1) a3v += __shfl_xor_sync(0xffffffffu, a3v, o);
            if (lane == 0) s_cl[wid] = a3v + W3b[wid];
        }
        __syncthreads();
        if (tid == 0) {
            float m = fmaxf(s_cl[0], fmaxf(s_cl[1], s_cl[2]));
            float e0 = __expf(s_cl[0]-m), e1 = __expf(s_cl[1]-m), e2 = __expf(s_cl[2]-m);
            float sm = e0 + e1 + e2;
            g_CHOICE[t*2+0] = __fdividef(e0, sm);
            g_CHOICE[t*2+1] = __fdividef(e1, sm);
        }

        // w2v[t] = W2b + sum_ky GP3[ky][t][:]
#pragma unroll
        for (int h2 = 0; h2 < 2; h2++) {
            int n = tid + 512*h2;
            float w = W2b[n];
#pragma unroll
            for (int ky = 0; ky < 8; ky++) w += g_GP3[ky*64*1024 + t*1024 + n];
            g_W2V[t*H + n] = w;
        }
        __syncthreads();
    }
    BAR_ARRIVE();
    BAR_WAIT(1);

    // cache step constants in smem (written by other blocks; visible after gen1)
    if (tid < S) {
        s_c0[tid]   = __ldcg(&g_CHOICE[tid*2+0]);
        s_c1[tid]   = __ldcg(&g_CHOICE[tid*2+1]);
        s_scal[tid] = __ldcg(&g_SCAL[tid]);
    }

    // logit0 partials -> p-major g_PART[0][blk][*]: reduce across g via shfls
    {
        float4 w4 = __ldcg((const float4*)(g_W2V + jc));
        float lp[8];
#pragma unroll
        for (int r = 0; r < 8; r++)
            lp[r] = evr[r].x*w4.x + evr[r].y*w4.y + evr[r].z*w4.z + evr[r].w*w4.w;
#pragma unroll
        for (int r = 0; r < 8; r++) {
            lp[r] += __shfl_xor_sync(0xffffffffu, lp[r], 1);
            lp[r] += __shfl_xor_sync(0xffffffffu, lp[r], 2);
            lp[r] += __shfl_xor_sync(0xffffffffu, lp[r], 4);
        }
        if (g == 0) {
            *(float4*)(g_PART[0] + blk*NE + i0)     = make_float4(lp[0], lp[1], lp[2], lp[3]);
            *(float4*)(g_PART[0] + blk*NE + i0 + 4) = make_float4(lp[4], lp[5], lp[6], lp[7]);
        }
    }
    BAR_ARRIVE();
    BAR_WAIT(2);

    // ========================= 64 sequential steps =========================
    float prevE = 0.f;   // previous ent for entity tid
    for (int t = 0; t < S; t++) {
        float c0   = s_c0[t];
        float c1   = s_c1[t];
        float scal = s_scal[t];

        // gather entity tid's 32 partials, p-major (coalesced)
        const float* pp = g_PART[t & 1] + tid;
        float q0 = 0.f, q1 = 0.f, q2 = 0.f, q3 = 0.f;
#pragma unroll
        for (int bb = 0; bb < RB; bb += 4) {
            q0 += __ldcg(pp + (bb+0)*NE);
            q1 += __ldcg(pp + (bb+1)*NE);
            q2 += __ldcg(pp + (bb+2)*NE);
            q3 += __ldcg(pp + (bb+3)*NE);
        }
        float lg = (q0 + q1) + (q2 + q3);
        float ent = __fdividef(1.f, 1.f + __expf(-lg));
        float at = fmaf(c0, ent, c1*prevE);
        prevE = ent;
        s_attn[tid] = at;
        __syncthreads();

        // asum: redundant per-warp sum of s_attn (conflict-free LDS.128)
        float asum;
        {
            float4 t0 = *(const float4*)&s_attn[lane*4];
            float4 t1 = *(const float4*)&s_attn[lane*4 + 128];
            float4 t2 = *(const float4*)&s_attn[lane*4 + 256];
            float4 t3 = *(const float4*)&s_attn[lane*4 + 384];
            float v = ((t0.x+t0.y)+(t0.z+t0.w)) + ((t1.x+t1.y)+(t1.z+t1.w))
                    + ((t2.x+t2.y)+(t2.z+t2.w)) + ((t3.x+t3.y)+(t3.z+t3.w));
#pragma unroll
            for (int o = 16; o; o >>= 1) v += __shfl_xor_sync(0xffffffffu, v, o);
            asum = v;
        }

        // bar_et partial: per-thread float4 over 8 rows; reduce s within warp
        float4 bacc = make_float4(0.f, 0.f, 0.f, 0.f);
#pragma unroll
        for (int r = 0; r < 8; r++) {
            float a = s_attn[i0 + r];
            bacc.x = fmaf(a, evr[r].x, bacc.x);
            bacc.y = fmaf(a, evr[r].y, bacc.y);
            bacc.z = fmaf(a, evr[r].z, bacc.z);
            bacc.w = fmaf(a, evr[r].w, bacc.w);
        }
#pragma unroll
        for (int o = 8; o <= 16; o <<= 1) {
            bacc.x += __shfl_xor_sync(0xffffffffu, bacc.x, o);
            bacc.y += __shfl_xor_sync(0xffffffffu, bacc.y, o);
            bacc.z += __shfl_xor_sync(0xffffffffu, bacc.z, o);
            bacc.w += __shfl_xor_sync(0xffffffffu, bacc.w, o);
        }
        if (lane < 8) *(float4*)&s_pc[wid][lane][0] = bacc;
        __syncthreads();
        if (tid < RC) {
            int gg = tid >> 2, cc = tid & 3;
            float bs = 0.f;
#pragma unroll
            for (int w = 0; w < 16; w++) bs += s_pc[w][gg][cc];
            float bar = __fdividef(bs, asum);
            out[OFF_ENT + t*H + blk*RC + tid] = bar;
            s_kt[tid] = fmaxf(scal*bar, 0.f);
        }
        __syncthreads();
        float4 kt4 = *(const float4*)&s_kt[g*4];

        if (t < S-1) {
            // update ev + next-step logit partials (3 shfls, 2x STG.128)
            float4 w4 = __ldcg((const float4*)(g_W2V + (t+1)*H + jc));
            float lp[8];
#pragma unroll
            for (int r = 0; r < 8; r++) {
                float a = s_attn[i0 + r];
                evr[r].x = fmaf(a, kt4.x - evr[r].x, evr[r].x);
                evr[r].y = fmaf(a, kt4.y - evr[r].y, evr[r].y);
                evr[r].z = fmaf(a, kt4.z - evr[r].z, evr[r].z);
                evr[r].w = fmaf(a, kt4.w - evr[r].w, evr[r].w);
                lp[r] = evr[r].x*w4.x + evr[r].y*w4.y + evr[r].z*w4.z + evr[r].w*w4.w;
            }
#pragma unroll
            for (int r = 0; r < 8; r++) {
                lp[r] += __shfl_xor_sync(0xffffffffu, lp[r], 1);
                lp[r] += __shfl_xor_sync(0xffffffffu, lp[r], 2);
                lp[r] += __shfl_xor_sync(0xffffffffu, lp[r], 4);
            }
            if (g == 0) {
                float* po = g_PART[(t+1) & 1] + blk*NE + i0;
                *(float4*)(po)     = make_float4(lp[0], lp[1], lp[2], lp[3]);
                *(float4*)(po + 4) = make_float4(lp[4], lp[5], lp[6], lp[7]);
            }

            // arrive orders only the partial store; outputs drain off-path.
            BAR_ARRIVE();
            // distributed ent_probs write: block blk writes entities [16blk,16blk+16)
            if ((tid >> 4) == blk) out[OFF_ENTP + t*NE + tid] = ent;
            {
                float* snap = out + OFF_ALL + (size_t)t*NE*H + jc;
#pragma unroll
                for (int r = 0; r < 8; r++)
                    __stcs((float4*)(snap + (size_t)(i0 + r)*H), evr[r]);
            }
            BAR_WAIT(3 + t);
        } else {
#pragma unroll
            for (int r = 0; r < 8; r++) {
                float a = s_attn[i0 + r];
                evr[r].x = fmaf(a, kt4.x - evr[r].x, evr[r].x);
                evr[r].y = fmaf(a, kt4.y - evr[r].y, evr[r].y);
                evr[r].z = fmaf(a, kt4.z - evr[r].z, evr[r].z);
                evr[r].w = fmaf(a, kt4.w - evr[r].w, evr[r].w);
            }
            if ((tid >> 4) == blk) out[OFF_ENTP + t*NE + tid] = ent;
            float* snap = out + OFF_ALL + (size_t)t*NE*H + jc;
#pragma unroll
            for (int r = 0; r < 8; r++)
                __stcs((float4*)(snap + (size_t)(i0 + r)*H), evr[r]);
        }
    }
#undef BAR_ARRIVE
#undef BAR_WAIT
}

// ---------------------------------------------------------------------------
extern "C" void kernel_launch(void* const* d_in, const int* in_sizes, int n_in,
                              void* d_out, int out_size)
{
    (void)in_sizes; (void)n_in; (void)out_size;
    const float* vv  = (const float*)d_in[0];
    const float* ev  = (const float*)d_in[1];
    const float* A1w = (const float*)d_in[2];
    const float* A1b = (const float*)d_in[3];
    const float* A2w = (const float*)d_in[4];
    const float* A2b = (const float*)d_in[5];
    const float* emb = (const float*)d_in[6];
    const float* W1w = (const float*)d_in[7];
    const float* W1b = (const float*)d_in[8];
    const float* W2w = (const float*)d_in[9];
    const float* W2b = (const float*)d_in[10];
    const float* W3w = (const float*)d_in[11];
    const float* W3b = (const float*)d_in[12];
    const float* W4w = (const float*)d_in[13];
    const float* W4b = (const float*)d_in[14];
    float* out = (float*)d_out;

    float *pHH, *pAC, *pGP3;
    cudaGetSymbolAddress((void**)&pHH,  g_HH);
    cudaGetSymbolAddress((void**)&pAC,  g_ACd);
    cudaGetSymbolAddress((void**)&pGP3, g_GP3);

    // 0: [h|hat] = relu(vv @ [A1w|W1w]^T + bias)  (also resets barrier counter)
    gemm32<<<dim3(64, 2), 256>>>(vv, H, A1w, W1w, 1024, A1b, W1b, pHH, 2048, H, 1);
    // 1: ac = sigmoid(h @ A2w^T + A2b)
    gemm32<<<dim3(16, 2), 256>>>(pHH, 2048, A2w, A2w, 1<<30, A2b, A2b, pAC, 512, H, 2);
    // 2: w2v partials
    gemm3<<<dim3(16, 8), 256>>>(W2w, pGP3, 1024, 1536, 192);
    // 3: fused finish + recurrence
    k_recurrent<<<RB, RT>>>(ev, emb, W2b, W3w, W3b, W4w, W4b, out);
}